// round 3
// baseline (speedup 1.0000x reference)
#include <cuda_runtime.h>
#include <math.h>

// support [25,2560] f32, query [4096,2560] f32 -> out [4096,5] f32
#define D      2560
#define NS     25
#define NQ     4096
#define NWAY   5
#define KSHOT  5
#define EPSV   1e-6f

#define NSPLIT 4
#define DQ     (D / NSPLIT)     // 640 cols per CTA
#define KT     128              // staged tile cols
#define NTILES (DQ / KT)        // 5
#define ROWS   32               // query rows per CTA
#define THREADS 256

typedef unsigned long long u64;

// partial results per d-quarter: [quarter][k][row], k: 0..24 dot, 25 qn, 26 qsum
__device__ float g_part[NSPLIT][27][NQ];
__device__ float g_ssq[NSPLIT][NS];
__device__ float g_ssum[NSPLIT][NS];

__device__ __forceinline__ u64 ffma2(u64 a, u64 b, u64 c) {
    u64 d;
    asm("fma.rn.f32x2 %0, %1, %2, %3;" : "=l"(d) : "l"(a), "l"(b), "l"(c));
    return d;
}
__device__ __forceinline__ u64 fadd2(u64 a, u64 b) {
    u64 d;
    asm("add.rn.f32x2 %0, %1, %2;" : "=l"(d) : "l"(a), "l"(b));
    return d;
}
__device__ __forceinline__ float f2_sum(u64 v) {
    return __uint_as_float((unsigned)(v & 0xffffffffull)) +
           __uint_as_float((unsigned)(v >> 32));
}

// ---------------------------------------------------------------------------
// Main: per (row-block, d-quarter) CTA. 8 warps x 4 rows = 32 rows.
// Lane = (rg 0..3, c 0..7): one row, 16B col slice -> 4-way smem multicast.
// Support tiles cp.async double-buffered (raw; eps folded algebraically).
// ---------------------------------------------------------------------------
__global__ __launch_bounds__(THREADS, 2)
void pd_main(const float* __restrict__ support,
             const float* __restrict__ query) {
    __shared__ float sS[2][NS][KT];
    __shared__ float s_red[NS][4][2];   // used only by blockIdx.x==0

    const int tid  = threadIdx.x;
    const int warp = tid >> 5;
    const int ln   = tid & 31;
    const int rg   = ln >> 3;
    const int c    = ln & 7;
    const int qd   = blockIdx.y;                 // d-quarter
    const int dstart = qd * DQ;
    const int row  = blockIdx.x * ROWS + warp * 4 + rg;
    const float* qrow = query + (size_t)row * D + dstart;
    const bool snorm_duty = (blockIdx.x == 0) && (tid < NS * 4);

    u64 acc[NS];
    #pragma unroll
    for (int s = 0; s < NS; ++s) acc[s] = 0ull;
    u64 qn2 = 0ull, qs2 = 0ull;
    float ssq = 0.f, ssm = 0.f;

    // ---- staging helper: tile t -> buffer buf (raw support, cp.async 16B) ----
    auto stage = [&](int t, int buf) {
        const int base = dstart + t * KT;
        #pragma unroll
        for (int i = tid; i < NS * (KT / 4); i += THREADS) {
            const int s  = i >> 5;          // KT/4 == 32 float4 per row
            const int c4 = (i & 31) * 4;
            const float* src = support + (size_t)s * D + base + c4;
            unsigned dst = (unsigned)__cvta_generic_to_shared(&sS[buf][s][c4]);
            asm volatile("cp.async.cg.shared.global [%0], [%1], 16;"
                         :: "r"(dst), "l"(src));
        }
        asm volatile("cp.async.commit_group;");
    };

    stage(0, 0);
    for (int t = 0; t < NTILES; ++t) {
        const int buf = t & 1;
        if (t + 1 < NTILES) {
            stage(t + 1, (t + 1) & 1);
            asm volatile("cp.async.wait_group 1;");
        } else {
            asm volatile("cp.async.wait_group 0;");
        }
        __syncthreads();

        const float* qt = qrow + t * KT;
        #pragma unroll
        for (int ch = 0; ch < KT / 32; ++ch) {
            const int col = ch * 32 + c * 4;
            const ulonglong2 qa = *reinterpret_cast<const ulonglong2*>(qt + col);
            qn2 = ffma2(qa.x, qa.x, qn2);
            qn2 = ffma2(qa.y, qa.y, qn2);
            qs2 = fadd2(qs2, qa.x);
            qs2 = fadd2(qs2, qa.y);
            #pragma unroll
            for (int s = 0; s < NS; ++s) {
                const ulonglong2 sv =
                    *reinterpret_cast<const ulonglong2*>(&sS[buf][s][col]);
                acc[s] = ffma2(qa.x, sv.x, acc[s]);
                acc[s] = ffma2(qa.y, sv.y, acc[s]);
            }
        }

        // snorm partials from the staged tile (only 4 CTAs, only 100 threads)
        if (snorm_duty) {
            const int s  = tid >> 2;
            const int qq = tid & 3;
            #pragma unroll
            for (int j = 0; j < 8; ++j) {
                const float4 v =
                    *reinterpret_cast<const float4*>(&sS[buf][s][qq * 32 + j * 4]);
                ssq = fmaf(v.x, v.x, ssq); ssq = fmaf(v.y, v.y, ssq);
                ssq = fmaf(v.z, v.z, ssq); ssq = fmaf(v.w, v.w, ssq);
                ssm += (v.x + v.y) + (v.z + v.w);
            }
        }
        __syncthreads();   // tile fully consumed before buffer reuse
    }

    // ---- reduce across the 8 c-lanes of each rg group ----
    float dot[NS];
    #pragma unroll
    for (int s = 0; s < NS; ++s) dot[s] = f2_sum(acc[s]);
    float qn = f2_sum(qn2), qs = f2_sum(qs2);
    #pragma unroll
    for (int off = 4; off > 0; off >>= 1) {
        #pragma unroll
        for (int s = 0; s < NS; ++s)
            dot[s] += __shfl_xor_sync(0xffffffffu, dot[s], off);
        qn += __shfl_xor_sync(0xffffffffu, qn, off);
        qs += __shfl_xor_sync(0xffffffffu, qs, off);
    }
    if (c == 0) {
        #pragma unroll
        for (int s = 0; s < NS; ++s) g_part[qd][s][row] = dot[s];
        g_part[qd][25][row] = qn;
        g_part[qd][26][row] = qs;
    }

    // ---- snorm partial write (blockIdx.x==0 only; single writer per slot) ----
    if (blockIdx.x == 0) {
        if (tid < NS * 4) {
            s_red[tid >> 2][tid & 3][0] = ssq;
            s_red[tid >> 2][tid & 3][1] = ssm;
        }
        __syncthreads();
        if (tid < NS) {
            float a = 0.f, b = 0.f;
            #pragma unroll
            for (int j = 0; j < 4; ++j) {
                a += s_red[tid][j][0];
                b += s_red[tid][j][1];
            }
            g_ssq[qd][tid]  = a;
            g_ssum[qd][tid] = b;
        }
    }
}

// ---------------------------------------------------------------------------
// Finish: combine quarters, dist = sqrt(qn + sn' - 2 dot - 2 eps qsum)
//         sn' = ssq + 2 eps ssum + D eps^2
// ---------------------------------------------------------------------------
__global__ void pd_finish(float* __restrict__ out) {
    __shared__ float sn[NS];
    if (threadIdx.x < NS) {
        float a = 0.f, b = 0.f;
        #pragma unroll
        for (int q = 0; q < NSPLIT; ++q) {
            a += g_ssq[q][threadIdx.x];
            b += g_ssum[q][threadIdx.x];
        }
        sn[threadIdx.x] = a + 2.f * EPSV * b + (float)D * EPSV * EPSV;
    }
    __syncthreads();

    const int row = blockIdx.x * blockDim.x + threadIdx.x;
    float dot[NS];
    #pragma unroll
    for (int s = 0; s < NS; ++s) dot[s] = 0.f;
    float qn = 0.f, qs = 0.f;
    #pragma unroll
    for (int q = 0; q < NSPLIT; ++q) {
        #pragma unroll
        for (int s = 0; s < NS; ++s) dot[s] += g_part[q][s][row];
        qn += g_part[q][25][row];
        qs += g_part[q][26][row];
    }
    const float base = qn - 2.f * EPSV * qs;
    #pragma unroll
    for (int w = 0; w < NWAY; ++w) {
        float sum = 0.f;
        #pragma unroll
        for (int k = 0; k < KSHOT; ++k) {
            const int s = w * KSHOT + k;
            const float d2 = base + sn[s] - 2.f * dot[s];
            sum += sqrtf(fmaxf(d2, 0.f));
        }
        out[(size_t)row * NWAY + w] = -sum;
    }
}

// ---------------------------------------------------------------------------
extern "C" void kernel_launch(void* const* d_in, const int* in_sizes, int n_in,
                              void* d_out, int out_size) {
    const float* support = (const float*)d_in[0];
    const float* query   = (const float*)d_in[1];
    if (n_in >= 2 && in_sizes[0] > in_sizes[1]) {
        const float* t = support; support = query; query = t;
    }
    float* out = (float*)d_out;

    pd_main<<<dim3(NQ / ROWS, NSPLIT), THREADS>>>(support, query);
    pd_finish<<<NQ / 128, 128>>>(out);
}

// round 4
// speedup vs baseline: 1.4890x; 1.4890x over previous
#include <cuda_runtime.h>
#include <math.h>

// support [25,2560] f32, query [4096,2560] f32 -> out [4096,5] f32
#define D       2560
#define NS      25
#define NQ      4096
#define NWAY    5
#define KSHOT   5
#define EPSV    1e-6f

#define NSPLIT  2
#define DQ      (D / NSPLIT)        // 1280 cols per CTA
#define KT      128                 // staged tile cols
#define NTILES  (DQ / KT)           // 10
#define ROWS    32                  // query rows per CTA
#define THREADS 256
#define NRB     (NQ / ROWS)         // 128 row blocks
#define NSH     13                  // supports per warp-half (1 overlap)

typedef unsigned long long u64;

// complete separable partial d^2 per half: [half][rowblock][row][s]
__device__ float g_pd2[NSPLIT][NRB][ROWS][NS];
__device__ int   g_ctr[NRB];        // zero-initialized; reset by finisher

__device__ __forceinline__ u64 ffma2(u64 a, u64 b, u64 c) {
    u64 d;
    asm("fma.rn.f32x2 %0, %1, %2, %3;" : "=l"(d) : "l"(a), "l"(b), "l"(c));
    return d;
}
__device__ __forceinline__ u64 fadd2(u64 a, u64 b) {
    u64 d;
    asm("add.rn.f32x2 %0, %1, %2;" : "=l"(d) : "l"(a), "l"(b));
    return d;
}
__device__ __forceinline__ float f2_sum(u64 v) {
    return __uint_as_float((unsigned)(v & 0xffffffffull)) +
           __uint_as_float((unsigned)(v >> 32));
}

// ---------------------------------------------------------------------------
// One CTA = (row block rb, D-half qd). 8 warps:
//   warp w: wp = w>>1 (row octet), half = w&1 (s-range: 0..12 / 12..24)
//   lane:   rg = ln>>3 (row pair within octet), c = ln&7 (16B col slice)
// Lane owns rows {base, base+1}, 13 supports, 4 cols/chunk.
// Support smem reads are 4-way multicast (8 distinct lanes -> 1 wavefront).
// Last-arriving CTA per row block fuses the sqrt/way-sum epilogue.
// ---------------------------------------------------------------------------
__global__ __launch_bounds__(THREADS, 2)
void pd_fused(const float* __restrict__ support,
              const float* __restrict__ query,
              float* __restrict__ out) {
    __shared__ float sS[2][NS][KT];       // double-buffered support tiles
    __shared__ float s_red[NS][8][2];     // ssq/ssm partials
    __shared__ float s_sn[NS];            // per-half support-norm term
    __shared__ float s_pd2[ROWS][NS];     // this CTA's partial d^2
    __shared__ int   s_flag;

    const int tid  = threadIdx.x;
    const int warp = tid >> 5;
    const int ln   = tid & 31;
    const int wp   = warp >> 1;           // row octet 0..3
    const int half = warp & 1;            // s-range selector
    const int rg   = ln >> 3;             // row pair 0..3
    const int c    = ln & 7;              // col group 0..7
    const int rb   = blockIdx.x;
    const int qd   = blockIdx.y;
    const int s0   = half * (NSH - 1);    // 0 or 12
    const int lrow = wp * 8 + rg * 2;     // local row (even)
    const int grow = rb * ROWS + lrow;
    const int dstart = qd * DQ;

    const float* qr0 = query + (size_t)grow * D + dstart;
    const float* qr1 = qr0 + D;

    u64 acc[NSH][2];
    #pragma unroll
    for (int j = 0; j < NSH; ++j) { acc[j][0] = 0ull; acc[j][1] = 0ull; }
    u64 qn0 = 0ull, qn1 = 0ull, qs0 = 0ull, qs1 = 0ull;
    float ssqA = 0.f, ssmA = 0.f;         // support-norm duty (tid < 200)
    const int sn_s   = tid >> 3;          // 0..31 (use <25 guard via tid<200)
    const int sn_oct = tid & 7;
    const bool sn_duty = (tid < NS * 8);

    // ---- cp.async staging: tile t -> buffer buf ----
    auto stage = [&](int t, int buf) {
        const int base = dstart + t * KT;
        #pragma unroll
        for (int i = tid; i < NS * (KT / 4); i += THREADS) {
            const int s  = i >> 5;               // KT/4 == 32
            const int c4 = (i & 31) * 4;
            const float* src = support + (size_t)s * D + base + c4;
            unsigned dst = (unsigned)__cvta_generic_to_shared(&sS[buf][s][c4]);
            asm volatile("cp.async.cg.shared.global [%0], [%1], 16;"
                         :: "r"(dst), "l"(src));
        }
        asm volatile("cp.async.commit_group;");
    };

    stage(0, 0);
    for (int t = 0; t < NTILES; ++t) {
        const int buf = t & 1;
        if (t + 1 < NTILES) {
            stage(t + 1, (t + 1) & 1);
            asm volatile("cp.async.wait_group 1;");
        } else {
            asm volatile("cp.async.wait_group 0;");
        }
        __syncthreads();

        const float* qt0 = qr0 + t * KT;
        const float* qt1 = qr1 + t * KT;
        #pragma unroll
        for (int ch = 0; ch < KT / 32; ++ch) {
            const int col = ch * 32 + c * 4;
            const ulonglong2 qa = *reinterpret_cast<const ulonglong2*>(qt0 + col);
            const ulonglong2 qb = *reinterpret_cast<const ulonglong2*>(qt1 + col);
            qn0 = ffma2(qa.x, qa.x, qn0); qn0 = ffma2(qa.y, qa.y, qn0);
            qn1 = ffma2(qb.x, qb.x, qn1); qn1 = ffma2(qb.y, qb.y, qn1);
            qs0 = fadd2(qs0, qa.x); qs0 = fadd2(qs0, qa.y);
            qs1 = fadd2(qs1, qb.x); qs1 = fadd2(qs1, qb.y);
            #pragma unroll
            for (int j = 0; j < NSH; ++j) {
                const ulonglong2 sv =
                    *reinterpret_cast<const ulonglong2*>(&sS[buf][s0 + j][col]);
                acc[j][0] = ffma2(qa.x, sv.x, acc[j][0]);
                acc[j][0] = ffma2(qa.y, sv.y, acc[j][0]);
                acc[j][1] = ffma2(qb.x, sv.x, acc[j][1]);
                acc[j][1] = ffma2(qb.y, sv.y, acc[j][1]);
            }
        }

        // support-norm partials straight from the staged tile (16 floats/thread)
        if (sn_duty) {
            #pragma unroll
            for (int j4 = 0; j4 < 4; ++j4) {
                const float4 v = *reinterpret_cast<const float4*>(
                    &sS[buf][sn_s][sn_oct * 16 + j4 * 4]);
                ssqA = fmaf(v.x, v.x, ssqA); ssqA = fmaf(v.y, v.y, ssqA);
                ssqA = fmaf(v.z, v.z, ssqA); ssqA = fmaf(v.w, v.w, ssqA);
                ssmA += (v.x + v.y) + (v.z + v.w);
            }
        }
        __syncthreads();   // tile fully consumed before buffer reuse
    }

    // ---- support-norm term: sn[s] = ssq + 2 eps ssm + DQ eps^2 ----
    if (sn_duty) {
        s_red[sn_s][sn_oct][0] = ssqA;
        s_red[sn_s][sn_oct][1] = ssmA;
    }
    __syncthreads();
    if (tid < NS) {
        float a = 0.f, b = 0.f;
        #pragma unroll
        for (int o = 0; o < 8; ++o) { a += s_red[tid][o][0]; b += s_red[tid][o][1]; }
        s_sn[tid] = a + 2.f * EPSV * b + (float)DQ * (EPSV * EPSV);
    }

    // ---- reduce across the 8 c-lanes (xor 1,2,4 stay within rg group) ----
    float dot0[NSH], dot1[NSH];
    #pragma unroll
    for (int j = 0; j < NSH; ++j) { dot0[j] = f2_sum(acc[j][0]); dot1[j] = f2_sum(acc[j][1]); }
    float fqn0 = f2_sum(qn0), fqn1 = f2_sum(qn1);
    float fqs0 = f2_sum(qs0), fqs1 = f2_sum(qs1);
    #pragma unroll
    for (int off = 4; off > 0; off >>= 1) {
        #pragma unroll
        for (int j = 0; j < NSH; ++j) {
            dot0[j] += __shfl_xor_sync(0xffffffffu, dot0[j], off);
            dot1[j] += __shfl_xor_sync(0xffffffffu, dot1[j], off);
        }
        fqn0 += __shfl_xor_sync(0xffffffffu, fqn0, off);
        fqn1 += __shfl_xor_sync(0xffffffffu, fqn1, off);
        fqs0 += __shfl_xor_sync(0xffffffffu, fqs0, off);
        fqs1 += __shfl_xor_sync(0xffffffffu, fqs1, off);
    }
    __syncthreads();   // s_sn ready

    // ---- partial d^2: qn + sn[s] - 2 dot - 2 eps qsum ----
    if (c == 0) {
        const float b0 = fqn0 - 2.f * EPSV * fqs0;
        const float b1 = fqn1 - 2.f * EPSV * fqs1;
        #pragma unroll
        for (int j = 0; j < NSH; ++j) {
            const int s = s0 + j;
            if (half == 0 || j > 0) {    // half1 skips duplicated s=12
                s_pd2[lrow][s]     = b0 + s_sn[s] - 2.f * dot0[j];
                s_pd2[lrow + 1][s] = b1 + s_sn[s] - 2.f * dot1[j];
            }
        }
    }
    __syncthreads();

    // ---- publish partials, then last-arriving CTA finishes the row block ----
    {
        float* gdst = &g_pd2[qd][rb][0][0];
        const float* ssrc = &s_pd2[0][0];
        #pragma unroll
        for (int i = tid; i < ROWS * NS; i += THREADS) gdst[i] = ssrc[i];
    }
    __threadfence();
    __syncthreads();
    if (tid == 0) s_flag = atomicAdd(&g_ctr[rb], 1);
    __syncthreads();

    if (s_flag == NSPLIT - 1) {
        // all other halves' stores are visible (they fenced before arriving)
        const int oq = 1 - qd;
        if (tid < ROWS * NWAY) {
            const int r = tid / NWAY;
            const int w = tid - r * NWAY;
            float sum = 0.f;
            #pragma unroll
            for (int k = 0; k < KSHOT; ++k) {
                const int s = w * KSHOT + k;
                const float d2 = s_pd2[r][s] + g_pd2[oq][rb][r][s];
                sum += sqrtf(fmaxf(d2, 0.f));
            }
            out[(size_t)(rb * ROWS + r) * NWAY + w] = -sum;
        }
        if (tid == 0) g_ctr[rb] = 0;   // reset for next graph replay
    }
}

// ---------------------------------------------------------------------------
extern "C" void kernel_launch(void* const* d_in, const int* in_sizes, int n_in,
                              void* d_out, int out_size) {
    const float* support = (const float*)d_in[0];
    const float* query   = (const float*)d_in[1];
    if (n_in >= 2 && in_sizes[0] > in_sizes[1]) {
        const float* t = support; support = query; query = t;
    }
    float* out = (float*)d_out;

    pd_fused<<<dim3(NRB, NSPLIT), THREADS>>>(support, query, out);
}

// round 6
// speedup vs baseline: 2.6334x; 1.7686x over previous
#include <cuda_runtime.h>
#include <cuda_bf16.h>
#include <math.h>
#include <string.h>

// support [25,2560] f32, query [4096,2560] f32 -> out [4096,5] f32
#define D       2560
#define NS      25
#define NSB     26              // 25 supports + 1 ones-row (gives qsum)
#define NPAD    32
#define NQ      4096
#define NWAY    5
#define KSHOT   5
#define EPSV    1e-6f

#define NSPLIT  4
#define DQ      640             // K per CTA
#define NCHUNK  40              // DQ / 16
#define MROWS   128             // query rows per CTA
#define NRB     32              // NQ / MROWS
#define THREADS 256
#define BSTRIDE 648             // bf16 elems per B smem row (bank-conflict-free)

typedef unsigned long long u64;

__device__ float g_dot[NSPLIT][NRB][NSB][MROWS];
__device__ float g_qn [NSPLIT][NRB][MROWS];
__device__ float g_sn [NSPLIT][NS];
__device__ int   g_ctr[NRB];    // zero-init; self-resetting per launch

__device__ __forceinline__ u64 ffma2(u64 a, u64 b, u64 c) {
    u64 d;
    asm("fma.rn.f32x2 %0, %1, %2, %3;" : "=l"(d) : "l"(a), "l"(b), "l"(c));
    return d;
}
__device__ __forceinline__ float f2_sum(u64 v) {
    return __uint_as_float((unsigned)(v & 0xffffffffull)) +
           __uint_as_float((unsigned)(v >> 32));
}
__device__ __forceinline__ u64 as_u64(float2 v) {
    u64 r; memcpy(&r, &v, 8); return r;
}
__device__ __forceinline__ unsigned cvt_bf2(float2 v) {
    __nv_bfloat162 p = __floats2bfloat162_rn(v.x, v.y);
    unsigned r; memcpy(&r, &p, 4); return r;
}

__device__ __forceinline__ void mma16816(float c[4],
                                         unsigned a0, unsigned a1,
                                         unsigned a2, unsigned a3,
                                         unsigned b0, unsigned b1) {
    asm volatile(
        "mma.sync.aligned.m16n8k16.row.col.f32.bf16.bf16.f32 "
        "{%0,%1,%2,%3}, {%4,%5,%6,%7}, {%8,%9}, {%0,%1,%2,%3};"
        : "+f"(c[0]), "+f"(c[1]), "+f"(c[2]), "+f"(c[3])
        : "r"(a0), "r"(a1), "r"(a2), "r"(a3), "r"(b0), "r"(b1));
}

// ---------------------------------------------------------------------------
// CTA = (row block rb, K-quarter qd). 8 warps, warp owns 16 query rows.
// B (support, bf16) staged once in smem: rows 0..24 data, row 25 = ones
// (dot with ones = qsum), rows 26..31 zero. A fragments loaded straight from
// global (float2 per lane, quad-coalesced), converted in registers; ||q||^2
// accumulated from the raw values with packed f32x2 FMAs.
// ---------------------------------------------------------------------------
__global__ __launch_bounds__(THREADS, 1)
void pd_mma(const float* __restrict__ support,
            const float* __restrict__ query,
            float* __restrict__ out) {
    __shared__ __align__(16) __nv_bfloat16 Bs[NPAD][BSTRIDE];
    __shared__ float s_red[NS][8][2];
    __shared__ float s_sn[NS];
    __shared__ int   s_flag;

    const int tid  = threadIdx.x;
    const int warp = tid >> 5;
    const int ln   = tid & 31;
    const int gid  = ln >> 2;        // quad row / n index
    const int tig  = ln & 3;         // position in quad
    const int rb   = blockIdx.x;
    const int qd   = blockIdx.y;
    const int dstart = qd * DQ;

    // ---- fill ones row (25) and zero pad rows (26..31) ----
    for (int i = tid; i < (NPAD - NS) * BSTRIDE; i += THREADS) {
        const int r = NS + i / BSTRIDE;
        const int c = i % BSTRIDE;
        Bs[r][c] = __float2bfloat16(r == NS ? 1.f : 0.f);
    }

    // ---- stage B: 25x640 f32 -> bf16 (rounded), plus ssq/ssm partials ----
    float ssq = 0.f, ssm = 0.f;
    if (tid < NS * 8) {
        const int n  = tid >> 3;
        const int kc = tid & 7;                    // 80-col strip
        const float* src = support + (size_t)n * D + dstart + kc * 80;
        #pragma unroll
        for (int j = 0; j < 20; ++j) {
            const float4 v = *reinterpret_cast<const float4*>(src + j * 4);
            const __nv_bfloat162 p0 = __floats2bfloat162_rn(v.x, v.y);
            const __nv_bfloat162 p1 = __floats2bfloat162_rn(v.z, v.w);
            const float r0 = __bfloat162float(p0.x), r1 = __bfloat162float(p0.y);
            const float r2 = __bfloat162float(p1.x), r3 = __bfloat162float(p1.y);
            ssq = fmaf(r0, r0, ssq); ssq = fmaf(r1, r1, ssq);
            ssq = fmaf(r2, r2, ssq); ssq = fmaf(r3, r3, ssq);
            ssm += (r0 + r1) + (r2 + r3);
            u64 u; memcpy(&u, &p0, 4); memcpy(((char*)&u) + 4, &p1, 4);
            *reinterpret_cast<u64*>(&Bs[n][kc * 80 + j * 4]) = u;
        }
        s_red[n][kc][0] = ssq;
        s_red[n][kc][1] = ssm;
    }
    __syncthreads();
    if (tid < NS) {
        float a = 0.f, b = 0.f;
        #pragma unroll
        for (int o = 0; o < 8; ++o) { a += s_red[tid][o][0]; b += s_red[tid][o][1]; }
        g_sn[qd][tid] = a + 2.f * EPSV * b;   // ||s~||^2 + 2 eps sum(s~) (quarter)
    }

    // ---- mainloop: 40 k-chunks of 16, 4 n-tiles of 8 ----
    const int lrow = warp * 16 + gid;                      // local row (0..127)
    const float* qa = query + (size_t)(rb * MROWS + lrow) * D + dstart + tig * 2;
    const float* qb = qa + (size_t)8 * D;                  // row +8

    float c[4][4];
    #pragma unroll
    for (int nt = 0; nt < 4; ++nt)
        #pragma unroll
        for (int i = 0; i < 4; ++i) c[nt][i] = 0.f;
    u64 qn0 = 0ull, qn1 = 0ull;

    const __nv_bfloat16* brow = &Bs[gid][tig * 2];

    #pragma unroll 2
    for (int ch = 0; ch < NCHUNK; ++ch) {
        const int k0 = ch * 16;
        const float2 a0 = *reinterpret_cast<const float2*>(qa + k0);
        const float2 a2 = *reinterpret_cast<const float2*>(qa + k0 + 8);
        const float2 a1 = *reinterpret_cast<const float2*>(qb + k0);
        const float2 a3 = *reinterpret_cast<const float2*>(qb + k0 + 8);
        qn0 = ffma2(as_u64(a0), as_u64(a0), qn0);
        qn0 = ffma2(as_u64(a2), as_u64(a2), qn0);
        qn1 = ffma2(as_u64(a1), as_u64(a1), qn1);
        qn1 = ffma2(as_u64(a3), as_u64(a3), qn1);
        const unsigned ra0 = cvt_bf2(a0);
        const unsigned ra1 = cvt_bf2(a1);
        const unsigned ra2 = cvt_bf2(a2);
        const unsigned ra3 = cvt_bf2(a3);
        #pragma unroll
        for (int nt = 0; nt < 4; ++nt) {
            const __nv_bfloat16* bp = brow + nt * 8 * BSTRIDE + k0;
            const unsigned b0 = *reinterpret_cast<const unsigned*>(bp);
            const unsigned b1 = *reinterpret_cast<const unsigned*>(bp + 8);
            mma16816(c[nt], ra0, ra1, ra2, ra3, b0, b1);
        }
    }

    // ---- qn: reduce over the 4 quad lanes (same row) ----
    float q0 = f2_sum(qn0), q1 = f2_sum(qn1);
    q0 += __shfl_xor_sync(0xffffffffu, q0, 1);
    q0 += __shfl_xor_sync(0xffffffffu, q0, 2);
    q1 += __shfl_xor_sync(0xffffffffu, q1, 1);
    q1 += __shfl_xor_sync(0xffffffffu, q1, 2);
    if (tig == 0) {
        g_qn[qd][rb][lrow]     = q0;
        g_qn[qd][rb][lrow + 8] = q1;
    }

    // ---- publish dot partials (c layout: rows gid/gid+8, cols tig*2/+1) ----
    #pragma unroll
    for (int nt = 0; nt < 4; ++nt) {
        const int s = nt * 8 + tig * 2;
        if (s < NSB) {
            g_dot[qd][rb][s][lrow]     = c[nt][0];
            g_dot[qd][rb][s][lrow + 8] = c[nt][2];
        }
        if (s + 1 < NSB) {
            g_dot[qd][rb][s + 1][lrow]     = c[nt][1];
            g_dot[qd][rb][s + 1][lrow + 8] = c[nt][3];
        }
    }

    __threadfence();
    __syncthreads();
    if (tid == 0) s_flag = atomicAdd(&g_ctr[rb], 1);
    __syncthreads();

    // ---- last CTA of this row block finishes ----
    if (s_flag == NSPLIT - 1) {
        if (tid < NS) {
            float a = 0.f;
            #pragma unroll
            for (int q = 0; q < NSPLIT; ++q) a += g_sn[q][tid];
            s_sn[tid] = a;
        }
        __syncthreads();
        if (tid < MROWS) {
            const int r = tid;
            float dt[NS];
            #pragma unroll
            for (int s = 0; s < NS; ++s) dt[s] = 0.f;
            float qnT = 0.f, qsT = 0.f;
            #pragma unroll
            for (int q = 0; q < NSPLIT; ++q) {
                #pragma unroll
                for (int s = 0; s < NS; ++s) dt[s] += g_dot[q][rb][s][r];
                qsT += g_dot[q][rb][25][r];     // ones-row dot = sum(q~)
                qnT += g_qn[q][rb][r];
            }
            // reference: e = s - q + eps
            // d2 = qn + (ssq + 2 eps ssm) + D eps^2 - 2 dot - 2 eps qsum
            const float base = qnT - 2.f * EPSV * qsT + (float)D * (EPSV * EPSV);
            #pragma unroll
            for (int w = 0; w < NWAY; ++w) {
                float sum = 0.f;
                #pragma unroll
                for (int k = 0; k < KSHOT; ++k) {
                    const int s = w * KSHOT + k;
                    const float d2 = base + s_sn[s] - 2.f * dt[s];
                    sum += sqrtf(fmaxf(d2, 0.f));
                }
                out[(size_t)(rb * MROWS + r) * NWAY + w] = -sum;
            }
        }
        if (tid == 0) g_ctr[rb] = 0;   // reset for next replay
    }
}

// ---------------------------------------------------------------------------
extern "C" void kernel_launch(void* const* d_in, const int* in_sizes, int n_in,
                              void* d_out, int out_size) {
    const float* support = (const float*)d_in[0];
    const float* query   = (const float*)d_in[1];
    if (n_in >= 2 && in_sizes[0] > in_sizes[1]) {
        const float* t = support; support = query; query = t;
    }
    float* out = (float*)d_out;

    pd_mma<<<dim3(NRB, NSPLIT), THREADS>>>(support, query, out);
}